// round 1
// baseline (speedup 1.0000x reference)
#include <cuda_runtime.h>
#include <math.h>

#define N_NODES   24000
#define NT_NODES  8000
#define NUM_T     3
#define NUM_R     34
#define EPR       10000
#define NH        8
#define DKQ       16
#define D         128

// ---------------- scratch (device globals; no allocation allowed) ----------
__device__ float g_k[N_NODES * D];
__device__ float g_q[N_NODES * D];
__device__ float g_v[N_NODES * D];
__device__ float g_qw[N_NODES * NH];
__device__ float g_kw[N_NODES * NH];
__device__ float g_e[NUM_R * EPR * NH];          // exp(score) per edge/head
__device__ float g_den[NUM_R * NT_NODES * NH];   // softmax denominators, compressed dst range
__device__ unsigned long long g_mask[N_NODES];   // relation bitmask per dst node
__device__ float g_nrelinv[N_NODES];
__device__ float g_t[N_NODES * D];               // aggregated messages

// relation -> node-type maps (compile-time formulas from reference)
__device__ __forceinline__ int src_nt(int r) { return r <= 9 ? 0 : (r <= 21 ? 1 : 2); }
__device__ __forceinline__ int dst_nt(int r) {
    if (r <= 2 || (r >= 10 && r <= 13) || (r >= 22 && r <= 24)) return 0;
    if ((r >= 3 && r <= 6) || (r >= 14 && r <= 17) || (r >= 25 && r <= 28)) return 1;
    return 2;
}

// ---------------- zero scratch that is accumulated into ---------------------
__global__ void zero_kernel() {
    int i0 = blockIdx.x * blockDim.x + threadIdx.x;
    int stride = gridDim.x * blockDim.x;
    float4 z = make_float4(0.f, 0.f, 0.f, 0.f);
    float4* den4 = (float4*)g_den;
    for (int i = i0; i < (NUM_R * NT_NODES * NH) / 4; i += stride) den4[i] = z;
    float4* t4 = (float4*)g_t;
    for (int i = i0; i < (N_NODES * D) / 4; i += stride) t4[i] = z;
    for (int i = i0; i < N_NODES; i += stride) g_mask[i] = 0ull;
}

// ---------------- typed K/Q/V projections (3 dense GEMMs per type) ----------
// grid: 375 blocks (64 nodes each; type boundaries at 8000 divide 64 cleanly)
__global__ __launch_bounds__(256) void proj3_kernel(
    const float* __restrict__ x,
    const float* __restrict__ Wk, const float* __restrict__ bk,
    const float* __restrict__ Wq, const float* __restrict__ bq,
    const float* __restrict__ Wv, const float* __restrict__ bv)
{
    __shared__ float xs[64 * D];
    __shared__ float ws[16 * D];
    int node0 = blockIdx.x * 64;
    int t = node0 / NT_NODES;
    int tid = threadIdx.x;
    {
        const float4* xg = (const float4*)(x + (size_t)node0 * D);
        float4* xs4 = (float4*)xs;
        #pragma unroll
        for (int i = 0; i < 8; i++) xs4[tid + i * 256] = xg[tid + i * 256];
    }
    __syncthreads();
    int col = (tid & 31) * 4;
    int row = (tid >> 5) * 8;
    const float* Wp[3] = { Wk + t * D * D, Wq + t * D * D, Wv + t * D * D };
    const float* bp[3] = { bk + t * D,     bq + t * D,     bv + t * D };
    float* op[3] = { g_k, g_q, g_v };
    for (int p = 0; p < 3; p++) {
        float acc[8][4];
        #pragma unroll
        for (int i = 0; i < 8; i++)
            #pragma unroll
            for (int j = 0; j < 4; j++) acc[i][j] = 0.f;
        for (int kc = 0; kc < 8; kc++) {
            __syncthreads();
            const float4* wg = (const float4*)(Wp[p] + kc * 16 * D);
            float4* ws4 = (float4*)ws;
            ws4[tid] = wg[tid];
            ws4[tid + 256] = wg[tid + 256];
            __syncthreads();
            #pragma unroll
            for (int kk = 0; kk < 16; kk++) {
                float4 w = *(const float4*)&ws[kk * D + col];
                #pragma unroll
                for (int i = 0; i < 8; i++) {
                    float xv = xs[(row + i) * D + kc * 16 + kk];
                    acc[i][0] += xv * w.x; acc[i][1] += xv * w.y;
                    acc[i][2] += xv * w.z; acc[i][3] += xv * w.w;
                }
            }
        }
        float4 bb = *(const float4*)&bp[p][col];
        float* o = op[p];
        #pragma unroll
        for (int i = 0; i < 8; i++) {
            float4 rr = make_float4(acc[i][0] + bb.x, acc[i][1] + bb.y,
                                    acc[i][2] + bb.z, acc[i][3] + bb.w);
            *(float4*)&o[(size_t)(node0 + row + i) * D + col] = rr;
        }
    }
}

// ---------------- per-node scalar attention terms q·wq, k·wk ----------------
__global__ void qkw_kernel(const float* __restrict__ attn_w) {
    int idx = blockIdx.x * blockDim.x + threadIdx.x;
    if (idx >= N_NODES * NH) return;
    // n*128 + h*16 == idx*16
    const float4* q4 = (const float4*)(g_q + (size_t)idx * DKQ);
    const float4* k4 = (const float4*)(g_k + (size_t)idx * DKQ);
    const float4* w4 = (const float4*)attn_w;
    float qs = 0.f, ks = 0.f;
    #pragma unroll
    for (int j = 0; j < 4; j++) {
        float4 q = q4[j], k = k4[j], wq = w4[j], wk = w4[4 + j];
        qs += q.x * wq.x + q.y * wq.y + q.z * wq.z + q.w * wq.w;
        ks += k.x * wk.x + k.y * wk.y + k.z * wk.z + k.w * wk.w;
    }
    g_qw[idx] = qs;
    g_kw[idx] = ks;
}

// ---------------- edge scores: e = exp(a + beta*na), den accumulation -------
// grid: (32, R); 256 threads = 32 edges x 8 heads
__global__ __launch_bounds__(256) void edge_score_kernel(
    const int* __restrict__ src, const int* __restrict__ dst,
    const float* __restrict__ rel_att, const float* __restrict__ rel_pri,
    const float* __restrict__ nta, const float* __restrict__ nta1,
    const float* __restrict__ weight)
{
    __shared__ float ratt[16 * 16 * NH];  // [d][f][h] for conflict-free lanes
    __shared__ float pri[NH];
    int r = blockIdx.y;
    int tid = threadIdx.x;
    #pragma unroll
    for (int it = 0; it < 8; it++) {
        int i = tid + it * 256;
        int hh = i >> 8, rem = i & 255, dd = rem >> 4, ff = rem & 15;
        ratt[(dd * 16 + ff) * NH + hh] = rel_att[r * 2048 + i];
    }
    if (tid < NH) pri[tid] = rel_pri[r * NH + tid] * 0.25f;  // fold 1/sqrt(16)
    __syncthreads();

    int snt = src_nt(r), dnt = dst_nt(r);
    float ntaS = nta[snt], ntaD = nta1[dnt];
    float beta = 1.f / (1.f + __expf(-weight[0]));

    int h = tid & 7;
    int el = tid >> 3;
    const float* rb = ratt + h;
    for (int e = blockIdx.x * 32 + el; e < EPR; e += 32 * gridDim.x) {
        int s = src[r * EPR + e];
        int d = dst[r * EPR + e];
        float kh[16], qh[16];
        const float4* kp = (const float4*)(g_k + (size_t)s * D + h * DKQ);
        const float4* qp = (const float4*)(g_q + (size_t)d * D + h * DKQ);
        #pragma unroll
        for (int j = 0; j < 4; j++) {
            float4 kv = kp[j];
            kh[j * 4] = kv.x; kh[j * 4 + 1] = kv.y; kh[j * 4 + 2] = kv.z; kh[j * 4 + 3] = kv.w;
            float4 qv = qp[j];
            qh[j * 4] = qv.x; qh[j * 4 + 1] = qv.y; qh[j * 4 + 2] = qv.z; qh[j * 4 + 3] = qv.w;
        }
        float a = 0.f;
        #pragma unroll
        for (int f = 0; f < 16; f++) {
            float kt = 0.f;
            #pragma unroll
            for (int dd = 0; dd < 16; dd++)
                kt += kh[dd] * rb[(dd * 16 + f) * NH];
            a += qh[f] * kt;
        }
        a *= pri[h];
        float na = ntaD * g_qw[(size_t)d * NH + h] + ntaS * g_kw[(size_t)s * NH + h];
        na = na > 0.f ? na : 0.01f * na;             // leaky_relu(0.01)
        float ev = __expf(a + beta * na);            // max-shift skipped (ratio-invariant)
        g_e[((size_t)r * EPR + e) * NH + h] = ev;
        atomicAdd(&g_den[((size_t)r * NT_NODES + (d - dnt * NT_NODES)) * NH + h], ev);
        if (h == 0) atomicOr(&g_mask[d], 1ull << r);
    }
}

// ---------------- nrel from relation bitmask ---------------------------------
__global__ void nrel_kernel() {
    int n = blockIdx.x * blockDim.x + threadIdx.x;
    if (n >= N_NODES) return;
    int c = __popcll(g_mask[n]);
    g_nrelinv[n] = 1.f / (float)(c > 0 ? c : 1);
}

// ---------------- message transform + weighted scatter into t ---------------
__global__ __launch_bounds__(256) void edge_accum_kernel(
    const int* __restrict__ src, const int* __restrict__ dst,
    const float* __restrict__ rel_msg)
{
    __shared__ float rm[16 * 16 * NH];  // [d][f][h]
    int r = blockIdx.y;
    int tid = threadIdx.x;
    #pragma unroll
    for (int it = 0; it < 8; it++) {
        int i = tid + it * 256;
        int hh = i >> 8, rem = i & 255, dd = rem >> 4, ff = rem & 15;
        rm[(dd * 16 + ff) * NH + hh] = rel_msg[r * 2048 + i];
    }
    __syncthreads();

    int dnt = dst_nt(r);
    int h = tid & 7;
    int el = tid >> 3;
    const float* rb = rm + h;
    for (int e = blockIdx.x * 32 + el; e < EPR; e += 32 * gridDim.x) {
        int s = src[r * EPR + e];
        int d = dst[r * EPR + e];
        float vh[16];
        const float4* vp = (const float4*)(g_v + (size_t)s * D + h * DKQ);
        #pragma unroll
        for (int j = 0; j < 4; j++) {
            float4 vv = vp[j];
            vh[j * 4] = vv.x; vh[j * 4 + 1] = vv.y; vh[j * 4 + 2] = vv.z; vh[j * 4 + 3] = vv.w;
        }
        float ev = g_e[((size_t)r * EPR + e) * NH + h];
        float den = g_den[((size_t)r * NT_NODES + (d - dnt * NT_NODES)) * NH + h];
        float w = (ev / den) * g_nrelinv[d];
        float* tp = g_t + (size_t)d * D + h * DKQ;
        #pragma unroll
        for (int f4 = 0; f4 < 4; f4++) {
            float o[4];
            #pragma unroll
            for (int j = 0; j < 4; j++) {
                int f = f4 * 4 + j;
                float val = 0.f;
                #pragma unroll
                for (int dd = 0; dd < 16; dd++)
                    val += vh[dd] * rb[(dd * 16 + f) * NH];
                o[j] = val * w;
            }
            asm volatile("red.global.add.v2.f32 [%0], {%1, %2};"
                         :: "l"(tp + f4 * 4), "f"(o[0]), "f"(o[1]) : "memory");
            asm volatile("red.global.add.v2.f32 [%0], {%1, %2};"
                         :: "l"(tp + f4 * 4 + 2), "f"(o[2]), "f"(o[3]) : "memory");
        }
    }
}

// ---------------- final typed projection + gated skip ------------------------
__global__ __launch_bounds__(256) void final_kernel(
    const float* __restrict__ x,
    const float* __restrict__ Wa, const float* __restrict__ ba,
    const float* __restrict__ skip, float* __restrict__ out)
{
    __shared__ float xs[64 * D];
    __shared__ float ws[16 * D];
    int node0 = blockIdx.x * 64;
    int t = node0 / NT_NODES;
    int tid = threadIdx.x;
    {
        const float4* tg = (const float4*)(g_t + (size_t)node0 * D);
        float4* xs4 = (float4*)xs;
        #pragma unroll
        for (int i = 0; i < 8; i++) xs4[tid + i * 256] = tg[tid + i * 256];
    }
    __syncthreads();
    int col = (tid & 31) * 4;
    int row = (tid >> 5) * 8;
    const float* Wp = Wa + t * D * D;
    float acc[8][4];
    #pragma unroll
    for (int i = 0; i < 8; i++)
        #pragma unroll
        for (int j = 0; j < 4; j++) acc[i][j] = 0.f;
    for (int kc = 0; kc < 8; kc++) {
        __syncthreads();
        const float4* wg = (const float4*)(Wp + kc * 16 * D);
        float4* ws4 = (float4*)ws;
        ws4[tid] = wg[tid];
        ws4[tid + 256] = wg[tid + 256];
        __syncthreads();
        #pragma unroll
        for (int kk = 0; kk < 16; kk++) {
            float4 w = *(const float4*)&ws[kk * D + col];
            #pragma unroll
            for (int i = 0; i < 8; i++) {
                float xv = xs[(row + i) * D + kc * 16 + kk];
                acc[i][0] += xv * w.x; acc[i][1] += xv * w.y;
                acc[i][2] += xv * w.z; acc[i][3] += xv * w.w;
            }
        }
    }
    float alpha = 1.f / (1.f + __expf(-skip[t]));
    float onema = 1.f - alpha;
    float4 bb = *(const float4*)&ba[t * D + col];
    #pragma unroll
    for (int i = 0; i < 8; i++) {
        size_t off = (size_t)(node0 + row + i) * D + col;
        float4 xv = *(const float4*)&x[off];
        float4 rr;
        rr.x = (acc[i][0] + bb.x) * alpha + xv.x * onema;
        rr.y = (acc[i][1] + bb.y) * alpha + xv.y * onema;
        rr.z = (acc[i][2] + bb.z) * alpha + xv.z * onema;
        rr.w = (acc[i][3] + bb.w) * alpha + xv.w * onema;
        *(float4*)&out[off] = rr;
    }
}

// ---------------- launch ------------------------------------------------------
extern "C" void kernel_launch(void* const* d_in, const int* in_sizes, int n_in,
                              void* d_out, int out_size)
{
    const float* x       = (const float*)d_in[0];
    const int*   src     = (const int*)  d_in[1];
    const int*   dst     = (const int*)  d_in[2];
    const float* Wk      = (const float*)d_in[3];
    const float* bk      = (const float*)d_in[4];
    const float* Wq      = (const float*)d_in[5];
    const float* bq      = (const float*)d_in[6];
    const float* Wv      = (const float*)d_in[7];
    const float* bv      = (const float*)d_in[8];
    const float* Wa      = (const float*)d_in[9];
    const float* ba      = (const float*)d_in[10];
    const float* rel_att = (const float*)d_in[11];
    const float* rel_msg = (const float*)d_in[12];
    const float* rel_pri = (const float*)d_in[13];
    const float* nta     = (const float*)d_in[14];
    const float* nta1    = (const float*)d_in[15];
    const float* skip    = (const float*)d_in[16];
    const float* weight  = (const float*)d_in[17];
    const float* attn_w  = (const float*)d_in[18];
    float* out = (float*)d_out;

    zero_kernel<<<1024, 256>>>();
    proj3_kernel<<<N_NODES / 64, 256>>>(x, Wk, bk, Wq, bq, Wv, bv);
    qkw_kernel<<<(N_NODES * NH + 255) / 256, 256>>>(attn_w);
    edge_score_kernel<<<dim3(32, NUM_R), 256>>>(src, dst, rel_att, rel_pri, nta, nta1, weight);
    nrel_kernel<<<(N_NODES + 255) / 256, 256>>>();
    edge_accum_kernel<<<dim3(32, NUM_R), 256>>>(src, dst, rel_msg);
    final_kernel<<<N_NODES / 64, 256>>>(x, Wa, ba, skip, out);
}

// round 2
// speedup vs baseline: 1.0709x; 1.0709x over previous
#include <cuda_runtime.h>
#include <math.h>

#define N_NODES   24000
#define NT_NODES  8000
#define NUM_T     3
#define NUM_R     34
#define EPR       10000
#define NH        8
#define DKQ       16
#define D         128

// ---------------- scratch (device globals; no allocation allowed) ----------
__device__ float g_k[N_NODES * D];
__device__ float g_q[N_NODES * D];
__device__ float g_v[N_NODES * D];
__device__ float g_qw[N_NODES * NH];
__device__ float g_kw[N_NODES * NH];
__device__ float g_e[NUM_R * EPR * NH];          // exp(score) per edge/head
__device__ float g_den[NUM_R * NT_NODES * NH];   // softmax denominators, compressed dst range
__device__ unsigned long long g_mask[N_NODES];   // relation bitmask per dst node
__device__ float g_nrelinv[N_NODES];
__device__ float g_t[N_NODES * D];               // aggregated messages

// relation -> node-type maps (compile-time formulas from reference)
__device__ __forceinline__ int src_nt(int r) { return r <= 9 ? 0 : (r <= 21 ? 1 : 2); }
__device__ __forceinline__ int dst_nt(int r) {
    if (r <= 2 || (r >= 10 && r <= 13) || (r >= 22 && r <= 24)) return 0;
    if ((r >= 3 && r <= 6) || (r >= 14 && r <= 17) || (r >= 25 && r <= 28)) return 1;
    return 2;
}

// ---------------- zero scratch that is accumulated into ---------------------
__global__ void zero_kernel() {
    int i0 = blockIdx.x * blockDim.x + threadIdx.x;
    int stride = gridDim.x * blockDim.x;
    float4 z = make_float4(0.f, 0.f, 0.f, 0.f);
    float4* den4 = (float4*)g_den;
    for (int i = i0; i < (NUM_R * NT_NODES * NH) / 4; i += stride) den4[i] = z;
    float4* t4 = (float4*)g_t;
    for (int i = i0; i < (N_NODES * D) / 4; i += stride) t4[i] = z;
    for (int i = i0; i < N_NODES; i += stride) g_mask[i] = 0ull;
}

// ---------------- typed K/Q/V projections (3 dense GEMMs per type) ----------
__global__ __launch_bounds__(256) void proj3_kernel(
    const float* __restrict__ x,
    const float* __restrict__ Wk, const float* __restrict__ bk,
    const float* __restrict__ Wq, const float* __restrict__ bq,
    const float* __restrict__ Wv, const float* __restrict__ bv)
{
    __shared__ float xs[64 * D];
    __shared__ float ws[16 * D];
    int node0 = blockIdx.x * 64;
    int t = node0 / NT_NODES;
    int tid = threadIdx.x;
    {
        const float4* xg = (const float4*)(x + (size_t)node0 * D);
        float4* xs4 = (float4*)xs;
        #pragma unroll
        for (int i = 0; i < 8; i++) xs4[tid + i * 256] = xg[tid + i * 256];
    }
    __syncthreads();
    int col = (tid & 31) * 4;
    int row = (tid >> 5) * 8;
    const float* Wp[3] = { Wk + t * D * D, Wq + t * D * D, Wv + t * D * D };
    const float* bp[3] = { bk + t * D,     bq + t * D,     bv + t * D };
    float* op[3] = { g_k, g_q, g_v };
    for (int p = 0; p < 3; p++) {
        float acc[8][4];
        #pragma unroll
        for (int i = 0; i < 8; i++)
            #pragma unroll
            for (int j = 0; j < 4; j++) acc[i][j] = 0.f;
        for (int kc = 0; kc < 8; kc++) {
            __syncthreads();
            const float4* wg = (const float4*)(Wp[p] + kc * 16 * D);
            float4* ws4 = (float4*)ws;
            ws4[tid] = wg[tid];
            ws4[tid + 256] = wg[tid + 256];
            __syncthreads();
            #pragma unroll
            for (int kk = 0; kk < 16; kk++) {
                float4 w = *(const float4*)&ws[kk * D + col];
                #pragma unroll
                for (int i = 0; i < 8; i++) {
                    float xv = xs[(row + i) * D + kc * 16 + kk];
                    acc[i][0] += xv * w.x; acc[i][1] += xv * w.y;
                    acc[i][2] += xv * w.z; acc[i][3] += xv * w.w;
                }
            }
        }
        float4 bb = *(const float4*)&bp[p][col];
        float* o = op[p];
        #pragma unroll
        for (int i = 0; i < 8; i++) {
            float4 rr = make_float4(acc[i][0] + bb.x, acc[i][1] + bb.y,
                                    acc[i][2] + bb.z, acc[i][3] + bb.w);
            *(float4*)&o[(size_t)(node0 + row + i) * D + col] = rr;
        }
    }
}

// ---------------- per-node scalar attention terms q·wq, k·wk ----------------
__global__ void qkw_kernel(const float* __restrict__ attn_w) {
    int idx = blockIdx.x * blockDim.x + threadIdx.x;
    if (idx >= N_NODES * NH) return;
    const float4* q4 = (const float4*)(g_q + (size_t)idx * DKQ);
    const float4* k4 = (const float4*)(g_k + (size_t)idx * DKQ);
    const float4* w4 = (const float4*)attn_w;
    float qs = 0.f, ks = 0.f;
    #pragma unroll
    for (int j = 0; j < 4; j++) {
        float4 q = q4[j], k = k4[j], wq = w4[j], wk = w4[4 + j];
        qs += q.x * wq.x + q.y * wq.y + q.z * wq.z + q.w * wq.w;
        ks += k.x * wk.x + k.y * wk.y + k.z * wk.z + k.w * wk.w;
    }
    g_qw[idx] = qs;
    g_kw[idx] = ks;
}

// ---------------- edge scores: e = exp(a + beta*na), den accumulation -------
// SMEM matrix layout: float4 tile indexed [(dd*4+f4)*8 + h] so a warp
// (4 edge-lanes x 8 head-lanes) issues one 128B conflict-free broadcast LDS.128.
__global__ __launch_bounds__(256) void edge_score_kernel(
    const int* __restrict__ src, const int* __restrict__ dst,
    const float* __restrict__ rel_att, const float* __restrict__ rel_pri,
    const float* __restrict__ nta, const float* __restrict__ nta1,
    const float* __restrict__ weight)
{
    __shared__ float4 ratt4[16 * 4 * NH];   // [dd][f4][h]
    __shared__ float pri[NH];
    int r = blockIdx.y;
    int tid = threadIdx.x;
    {
        float* ratt = (float*)ratt4;
        #pragma unroll
        for (int it = 0; it < 8; it++) {
            int i = tid + it * 256;                       // = h*256 + dd*16 + f
            int hh = i >> 8, dd = (i >> 4) & 15, ff = i & 15;
            ratt[((dd * 4 + (ff >> 2)) * NH + hh) * 4 + (ff & 3)] = rel_att[r * 2048 + i];
        }
    }
    if (tid < NH) pri[tid] = rel_pri[r * NH + tid] * 0.25f;  // fold 1/sqrt(16)
    __syncthreads();

    int snt = src_nt(r), dnt = dst_nt(r);
    float ntaS = nta[snt], ntaD = nta1[dnt];
    float beta = 1.f / (1.f + __expf(-weight[0]));

    int h = tid & 7;
    int el = tid >> 3;
    const float4* rb4 = ratt4 + h;
    for (int e = blockIdx.x * 32 + el; e < EPR; e += 32 * gridDim.x) {
        int s = src[r * EPR + e];
        int d = dst[r * EPR + e];
        float kh[16], qh[16];
        const float4* kp = (const float4*)(g_k + (size_t)s * D + h * DKQ);
        const float4* qp = (const float4*)(g_q + (size_t)d * D + h * DKQ);
        #pragma unroll
        for (int j = 0; j < 4; j++) {
            float4 kv = kp[j];
            kh[j * 4] = kv.x; kh[j * 4 + 1] = kv.y; kh[j * 4 + 2] = kv.z; kh[j * 4 + 3] = kv.w;
            float4 qv = qp[j];
            qh[j * 4] = qv.x; qh[j * 4 + 1] = qv.y; qh[j * 4 + 2] = qv.z; qh[j * 4 + 3] = qv.w;
        }
        float4 kt[4];
        #pragma unroll
        for (int f4 = 0; f4 < 4; f4++) kt[f4] = make_float4(0.f, 0.f, 0.f, 0.f);
        #pragma unroll
        for (int dd = 0; dd < 16; dd++) {
            float kd = kh[dd];
            #pragma unroll
            for (int f4 = 0; f4 < 4; f4++) {
                float4 a4 = rb4[(dd * 4 + f4) * NH];
                kt[f4].x += kd * a4.x; kt[f4].y += kd * a4.y;
                kt[f4].z += kd * a4.z; kt[f4].w += kd * a4.w;
            }
        }
        float a = 0.f;
        #pragma unroll
        for (int f4 = 0; f4 < 4; f4++) {
            a += kt[f4].x * qh[f4 * 4]     + kt[f4].y * qh[f4 * 4 + 1]
               + kt[f4].z * qh[f4 * 4 + 2] + kt[f4].w * qh[f4 * 4 + 3];
        }
        a *= pri[h];
        float na = ntaD * g_qw[(size_t)d * NH + h] + ntaS * g_kw[(size_t)s * NH + h];
        na = na > 0.f ? na : 0.01f * na;             // leaky_relu(0.01)
        float ev = __expf(a + beta * na);            // max-shift skipped (ratio-invariant)
        g_e[((size_t)r * EPR + e) * NH + h] = ev;
        atomicAdd(&g_den[((size_t)r * NT_NODES + (d - dnt * NT_NODES)) * NH + h], ev);
        if (h == 0) atomicOr(&g_mask[d], 1ull << r);
    }
}

// ---------------- nrel from relation bitmask ---------------------------------
__global__ void nrel_kernel() {
    int n = blockIdx.x * blockDim.x + threadIdx.x;
    if (n >= N_NODES) return;
    int c = __popcll(g_mask[n]);
    g_nrelinv[n] = 1.f / (float)(c > 0 ? c : 1);
}

// ---------------- message transform + weighted scatter into t ---------------
__global__ __launch_bounds__(256) void edge_accum_kernel(
    const int* __restrict__ src, const int* __restrict__ dst,
    const float* __restrict__ rel_msg)
{
    __shared__ float4 rm4[16 * 4 * NH];   // [dd][f4][h]
    int r = blockIdx.y;
    int tid = threadIdx.x;
    {
        float* rm = (float*)rm4;
        #pragma unroll
        for (int it = 0; it < 8; it++) {
            int i = tid + it * 256;
            int hh = i >> 8, dd = (i >> 4) & 15, ff = i & 15;
            rm[((dd * 4 + (ff >> 2)) * NH + hh) * 4 + (ff & 3)] = rel_msg[r * 2048 + i];
        }
    }
    __syncthreads();

    int dnt = dst_nt(r);
    int h = tid & 7;
    int el = tid >> 3;
    const float4* rb4 = rm4 + h;
    for (int e = blockIdx.x * 32 + el; e < EPR; e += 32 * gridDim.x) {
        int s = src[r * EPR + e];
        int d = dst[r * EPR + e];
        float ev = g_e[((size_t)r * EPR + e) * NH + h];
        float den = g_den[((size_t)r * NT_NODES + (d - dnt * NT_NODES)) * NH + h];
        float w = (ev / den) * g_nrelinv[d];
        float vh[16];
        const float4* vp = (const float4*)(g_v + (size_t)s * D + h * DKQ);
        #pragma unroll
        for (int j = 0; j < 4; j++) {
            float4 vv = vp[j];
            vh[j * 4] = vv.x * w; vh[j * 4 + 1] = vv.y * w;
            vh[j * 4 + 2] = vv.z * w; vh[j * 4 + 3] = vv.w * w;
        }
        float4 o[4];
        #pragma unroll
        for (int f4 = 0; f4 < 4; f4++) o[f4] = make_float4(0.f, 0.f, 0.f, 0.f);
        #pragma unroll
        for (int dd = 0; dd < 16; dd++) {
            float vd = vh[dd];
            #pragma unroll
            for (int f4 = 0; f4 < 4; f4++) {
                float4 a4 = rb4[(dd * 4 + f4) * NH];
                o[f4].x += vd * a4.x; o[f4].y += vd * a4.y;
                o[f4].z += vd * a4.z; o[f4].w += vd * a4.w;
            }
        }
        float* tp = g_t + (size_t)d * D + h * DKQ;
        #pragma unroll
        for (int f4 = 0; f4 < 4; f4++) {
            asm volatile("red.global.add.v4.f32 [%0], {%1, %2, %3, %4};"
                         :: "l"(tp + f4 * 4),
                            "f"(o[f4].x), "f"(o[f4].y), "f"(o[f4].z), "f"(o[f4].w)
                         : "memory");
        }
    }
}

// ---------------- final typed projection + gated skip ------------------------
__global__ __launch_bounds__(256) void final_kernel(
    const float* __restrict__ x,
    const float* __restrict__ Wa, const float* __restrict__ ba,
    const float* __restrict__ skip, float* __restrict__ out)
{
    __shared__ float xs[64 * D];
    __shared__ float ws[16 * D];
    int node0 = blockIdx.x * 64;
    int t = node0 / NT_NODES;
    int tid = threadIdx.x;
    {
        const float4* tg = (const float4*)(g_t + (size_t)node0 * D);
        float4* xs4 = (float4*)xs;
        #pragma unroll
        for (int i = 0; i < 8; i++) xs4[tid + i * 256] = tg[tid + i * 256];
    }
    __syncthreads();
    int col = (tid & 31) * 4;
    int row = (tid >> 5) * 8;
    const float* Wp = Wa + t * D * D;
    float acc[8][4];
    #pragma unroll
    for (int i = 0; i < 8; i++)
        #pragma unroll
        for (int j = 0; j < 4; j++) acc[i][j] = 0.f;
    for (int kc = 0; kc < 8; kc++) {
        __syncthreads();
        const float4* wg = (const float4*)(Wp + kc * 16 * D);
        float4* ws4 = (float4*)ws;
        ws4[tid] = wg[tid];
        ws4[tid + 256] = wg[tid + 256];
        __syncthreads();
        #pragma unroll
        for (int kk = 0; kk < 16; kk++) {
            float4 w = *(const float4*)&ws[kk * D + col];
            #pragma unroll
            for (int i = 0; i < 8; i++) {
                float xv = xs[(row + i) * D + kc * 16 + kk];
                acc[i][0] += xv * w.x; acc[i][1] += xv * w.y;
                acc[i][2] += xv * w.z; acc[i][3] += xv * w.w;
            }
        }
    }
    float alpha = 1.f / (1.f + __expf(-skip[t]));
    float onema = 1.f - alpha;
    float4 bb = *(const float4*)&ba[t * D + col];
    #pragma unroll
    for (int i = 0; i < 8; i++) {
        size_t off = (size_t)(node0 + row + i) * D + col;
        float4 xv = *(const float4*)&x[off];
        float4 rr;
        rr.x = (acc[i][0] + bb.x) * alpha + xv.x * onema;
        rr.y = (acc[i][1] + bb.y) * alpha + xv.y * onema;
        rr.z = (acc[i][2] + bb.z) * alpha + xv.z * onema;
        rr.w = (acc[i][3] + bb.w) * alpha + xv.w * onema;
        *(float4*)&out[off] = rr;
    }
}

// ---------------- launch ------------------------------------------------------
extern "C" void kernel_launch(void* const* d_in, const int* in_sizes, int n_in,
                              void* d_out, int out_size)
{
    const float* x       = (const float*)d_in[0];
    const int*   src     = (const int*)  d_in[1];
    const int*   dst     = (const int*)  d_in[2];
    const float* Wk      = (const float*)d_in[3];
    const float* bk      = (const float*)d_in[4];
    const float* Wq      = (const float*)d_in[5];
    const float* bq      = (const float*)d_in[6];
    const float* Wv      = (const float*)d_in[7];
    const float* bv      = (const float*)d_in[8];
    const float* Wa      = (const float*)d_in[9];
    const float* ba      = (const float*)d_in[10];
    const float* rel_att = (const float*)d_in[11];
    const float* rel_msg = (const float*)d_in[12];
    const float* rel_pri = (const float*)d_in[13];
    const float* nta     = (const float*)d_in[14];
    const float* nta1    = (const float*)d_in[15];
    const float* skip    = (const float*)d_in[16];
    const float* weight  = (const float*)d_in[17];
    const float* attn_w  = (const float*)d_in[18];
    float* out = (float*)d_out;

    zero_kernel<<<1024, 256>>>();
    proj3_kernel<<<N_NODES / 64, 256>>>(x, Wk, bk, Wq, bq, Wv, bv);
    qkw_kernel<<<(N_NODES * NH + 255) / 256, 256>>>(attn_w);
    edge_score_kernel<<<dim3(32, NUM_R), 256>>>(src, dst, rel_att, rel_pri, nta, nta1, weight);
    nrel_kernel<<<(N_NODES + 255) / 256, 256>>>();
    edge_accum_kernel<<<dim3(32, NUM_R), 256>>>(src, dst, rel_msg);
    final_kernel<<<N_NODES / 64, 256>>>(x, Wa, ba, skip, out);
}